// round 16
// baseline (speedup 1.0000x reference)
#include <cuda_runtime.h>
#include <cuda_fp16.h>
#include <cstdint>

#define D_MODEL 1024
#define NHEAD   16
#define DHEAD   64
#define SEQ     2048
#define BATCH   2
#define M_TOTAL (BATCH * SEQ)   /* 4096 */
#define RANK    32

// ---------------- device scratch (all single fp16) ----------------
__device__ __half g_xh [(size_t)M_TOTAL * D_MODEL];
__device__ __half g_w2 [(size_t)4 * D_MODEL * D_MODEL];
__device__ __half g_ao [(size_t)M_TOTAL * D_MODEL];
__device__ __half g_qh [(size_t)BATCH * NHEAD * SEQ * 64];  // Q * 0.125*log2e
__device__ __half g_kh [(size_t)BATCH * NHEAD * SEQ * 64];
__device__ __half g_vh [(size_t)BATCH * NHEAD * SEQ * 64];

// ---------------- PTX helpers (baseline PTX only) ----------------
__device__ __forceinline__ uint32_t smem_u32(const void* p) {
    uint32_t a;
    asm("{ .reg .u64 t; cvta.to.shared.u64 t, %1; cvt.u32.u64 %0, t; }" : "=r"(a) : "l"(p));
    return a;
}
__device__ __forceinline__ void cpa16(uint32_t dst, const void* src) {
    asm volatile("cp.async.cg.shared.global [%0], [%1], 16;" :: "r"(dst), "l"(src));
}
#define CP_COMMIT() asm volatile("cp.async.commit_group;" ::: "memory")
#define CP_WAIT(n)  asm volatile("cp.async.wait_group %0;" :: "n"(n) : "memory")

__device__ __forceinline__ void ldsm_x4(uint32_t (&r)[4], uint32_t addr) {
    asm volatile("ldmatrix.sync.aligned.m8n8.x4.shared.b16 {%0,%1,%2,%3}, [%4];"
                 : "=r"(r[0]), "=r"(r[1]), "=r"(r[2]), "=r"(r[3]) : "r"(addr));
}
__device__ __forceinline__ void ldsm_x4t(uint32_t (&r)[4], uint32_t addr) {
    asm volatile("ldmatrix.sync.aligned.m8n8.x4.trans.shared.b16 {%0,%1,%2,%3}, [%4];"
                 : "=r"(r[0]), "=r"(r[1]), "=r"(r[2]), "=r"(r[3]) : "r"(addr));
}
__device__ __forceinline__ void mma16816h(float (&d)[4], const uint32_t (&a)[4],
                                          uint32_t b0, uint32_t b1) {
    asm volatile("mma.sync.aligned.m16n8k16.row.col.f32.f16.f16.f32 "
                 "{%0,%1,%2,%3}, {%4,%5,%6,%7}, {%8,%9}, {%0,%1,%2,%3};"
                 : "+f"(d[0]), "+f"(d[1]), "+f"(d[2]), "+f"(d[3])
                 : "r"(a[0]), "r"(a[1]), "r"(a[2]), "r"(a[3]), "r"(b0), "r"(b1));
}
__device__ __forceinline__ void mma16816hh(uint32_t (&d)[2], const uint32_t (&a)[4],
                                           uint32_t b0, uint32_t b1) {
    asm volatile("mma.sync.aligned.m16n8k16.row.col.f16.f16.f16.f16 "
                 "{%0,%1}, {%2,%3,%4,%5}, {%6,%7}, {%0,%1};"
                 : "+r"(d[0]), "+r"(d[1])
                 : "r"(a[0]), "r"(a[1]), "r"(a[2]), "r"(a[3]), "r"(b0), "r"(b1));
}
__device__ __forceinline__ uint32_t packh2(float v0, float v1) {
    __half2 t = __floats2half2_rn(v0, v1);
    return reinterpret_cast<uint32_t&>(t);
}
__device__ __forceinline__ float ex2(float x) {
    float y;
    asm("ex2.approx.ftz.f32 %0, %1;" : "=f"(y) : "f"(x));
    return y;
}
__device__ __forceinline__ uint32_t hmax2(uint32_t a, uint32_t b) {
    uint32_t d;
    asm("max.f16x2 %0, %1, %2;" : "=r"(d) : "r"(a), "r"(b));
    return d;
}

// ---------------- smem-tiled LoRA merge (unchanged, known-good) ------------
__global__ void __launch_bounds__(256)
merge_lora_t(const float* __restrict__ W0, const float* __restrict__ dW0, const float* __restrict__ dB0,
             const float* __restrict__ W1, const float* __restrict__ dW1, const float* __restrict__ dB1,
             const float* __restrict__ W2, const float* __restrict__ dW2, const float* __restrict__ dB2,
             const float* __restrict__ W3, const float* __restrict__ dW3, const float* __restrict__ dB3)
{
    const int kx = blockIdx.x;
    const int ny = blockIdx.y;
    const int layer = blockIdx.z;
    const float* W  = (layer == 0) ? W0  : (layer == 1) ? W1  : (layer == 2) ? W2  : W3;
    const float* dW = (layer == 0) ? dW0 : (layer == 1) ? dW1 : (layer == 2) ? dW2 : dW3;
    const float* dB = (layer == 0) ? dB0 : (layer == 1) ? dB1 : (layer == 2) ? dB2 : dB3;

    __shared__ float4 dws[RANK][64];
    __shared__ float  dbs[32][RANK];

    const int tid = threadIdx.x;
    const float4* dW4 = (const float4*)dW;
    const int n0 = ny * 32;

#pragma unroll
    for (int i = 0; i < 8; i++) {
        int e = tid + i * 256;
        int r = e >> 6, q = e & 63;
        dws[r][q] = dW4[r * 256 + kx * 64 + q];
    }
#pragma unroll
    for (int i = 0; i < 4; i++) {
        int e = tid + i * 256;
        int row = e >> 5, r = e & 31;
        dbs[row][r] = dB[(n0 + row) * RANK + r];
    }
    __syncthreads();

    const int q    = tid & 63;
    const int rowg = tid >> 6;
    const float4* W4 = (const float4*)W;
    float4 s[8];
#pragma unroll
    for (int j = 0; j < 8; j++)
        s[j] = W4[(size_t)(n0 + rowg * 8 + j) * 256 + kx * 64 + q];
#pragma unroll
    for (int r = 0; r < RANK; r++) {
        float4 w = dws[r][q];
#pragma unroll
        for (int j = 0; j < 8; j++) {
            float b = dbs[rowg * 8 + j][r];
            s[j].x += b * w.x; s[j].y += b * w.y;
            s[j].z += b * w.z; s[j].w += b * w.w;
        }
    }
#pragma unroll
    for (int j = 0; j < 8; j++) {
        int n = n0 + rowg * 8 + j;
        __half2* p = (__half2*)(g_w2 + (size_t)(layer * D_MODEL + n) * D_MODEL
                                + (kx * 64 + q) * 4);
        p[0] = __floats2half2_rn(s[j].x, s[j].y);
        p[1] = __floats2half2_rn(s[j].z, s[j].w);
    }
}

// ---------------- x -> single fp16 ----------------
__global__ void prep_h(const float* __restrict__ src)
{
    int e = blockIdx.x * 256 + threadIdx.x;
    float4 s = *(const float4*)(src + (size_t)e * 4);
    __half2* p = (__half2*)(g_xh + (size_t)e * 4);
    p[0] = __floats2half2_rn(s.x, s.y);
    p[1] = __floats2half2_rn(s.z, s.w);
}

// ---------------- HMMA GEMM (unchanged from round 15) ----------------------
#define GKC   64
#define GNCH  16
#define GROWB 144
#define GA_BYTES (128 * GROWB)
#define GW_BYTES (64 * GROWB)
#define GSTAGE   (GA_BYTES + GW_BYTES)
#define GSMEM    (2 * GSTAGE)

__global__ void __launch_bounds__(256, 3)
gemm_hmma(const __half* __restrict__ Abase,
          int mode, int layer_base,
          const float* __restrict__ b0, const float* __restrict__ b1,
          const float* __restrict__ b2, float* __restrict__ outO)
{
    extern __shared__ __align__(128) char smem[];
    const uint32_t sb = smem_u32(smem);
    const int tid = threadIdx.x, ln = tid & 31, w = tid >> 5;
    const int wm = w & 3, wn = w >> 2;
    const int bx = blockIdx.x, by = blockIdx.y, z = blockIdx.z;
    const int layer = layer_base + z;

    const __half* Arow = Abase + (size_t)(by * 128) * D_MODEL;
    const __half* Wrow = g_w2 + ((size_t)layer * D_MODEL + bx * 64) * D_MODEL;

    float acc[2][4][4] = {};

#define GLOAD(c) do {                                                          \
        int s_ = (c) & 1;                                                      \
        int x_ = (c) * GKC;                                                    \
        uint32_t bA_ = sb + s_ * GSTAGE;                                       \
        uint32_t bW_ = bA_ + GA_BYTES;                                         \
        _Pragma("unroll")                                                      \
        for (int u_ = 0; u_ < 4; u_++) {                                       \
            int e_ = tid + u_ * 256;                                           \
            int row_ = e_ >> 3, seg_ = (e_ & 7) * 16;                          \
            cpa16(bA_ + row_ * GROWB + seg_,                                   \
                  (const char*)(Arow + (size_t)row_ * D_MODEL + x_) + seg_);   \
        }                                                                      \
        _Pragma("unroll")                                                      \
        for (int u_ = 0; u_ < 2; u_++) {                                       \
            int e_ = tid + u_ * 256;                                           \
            int row_ = e_ >> 3, seg_ = (e_ & 7) * 16;                          \
            cpa16(bW_ + row_ * GROWB + seg_,                                   \
                  (const char*)(Wrow + (size_t)row_ * D_MODEL + x_) + seg_);   \
        }                                                                      \
        CP_COMMIT();                                                           \
    } while (0)

    GLOAD(0);
    for (int c = 0; c < GNCH; c++) {
        CP_WAIT(0);
        __syncthreads();
        if (c + 1 < GNCH) GLOAD(c + 1);

        const uint32_t bA = sb + (c & 1) * GSTAGE;
        const uint32_t bW = bA + GA_BYTES;
#pragma unroll
        for (int ks = 0; ks < 4; ks++) {
            const int k0 = ks * 16;
            uint32_t afr[2][4];
#pragma unroll
            for (int i = 0; i < 2; i++) {
                int row = wm * 32 + i * 16 + (ln & 15);
                ldsm_x4(afr[i], bA + row * GROWB + (k0 + ((ln >> 4) << 3)) * 2);
            }
            uint32_t bfr[2][4];
#pragma unroll
            for (int j = 0; j < 2; j++) {
                int n = wn * 32 + j * 16 + (ln & 7) + ((ln & 16) ? 8 : 0);
                ldsm_x4(bfr[j], bW + n * GROWB + (k0 + ((ln & 8) ? 8 : 0)) * 2);
            }
#pragma unroll
            for (int i = 0; i < 2; i++)
#pragma unroll
                for (int jj = 0; jj < 4; jj++)
                    mma16816h(acc[i][jj], afr[i], bfr[jj >> 1][(jj & 1) * 2],
                              bfr[jj >> 1][(jj & 1) * 2 + 1]);
        }
    }

    const float* bias = (z == 0) ? b0 : (z == 1) ? b1 : b2;
    const float qscale = (mode == 0 && z == 0) ? 0.125f * 1.4426950408889634f : 1.0f;
#pragma unroll
    for (int i = 0; i < 2; i++) {
#pragma unroll
        for (int dl = 0; dl < 2; dl++) {
            const int m = by * 128 + wm * 32 + i * 16 + (ln >> 2) + dl * 8;
#pragma unroll
            for (int jj = 0; jj < 4; jj++) {
                const int cgl = bx * 64 + wn * 32 + jj * 8 + (ln & 3) * 2;
                float v0 = (acc[i][jj][dl * 2 + 0] + bias[cgl])     * qscale;
                float v1 = (acc[i][jj][dl * 2 + 1] + bias[cgl + 1]) * qscale;
                if (mode == 0) {
                    const int h = cgl >> 6, d = cgl & 63;
                    const int b = m >> 11, n = m & 2047;
                    const size_t rowb = (size_t)(b * NHEAD + h) * SEQ + n;
                    __half* base = ((z == 0) ? g_qh : (z == 1) ? g_kh : g_vh)
                                   + rowb * 64 + d;
                    *(__half2*)base = __floats2half2_rn(v0, v1);
                } else {
                    float2 o; o.x = v0; o.y = v1;
                    *(float2*)(outO + (size_t)m * D_MODEL + cgl) = o;
                }
            }
        }
    }
}

// ---------------- Flash attention: packed-fp16 S, 3 CTAs/SM ----------------
#define KROWB 144
#define KTILEB (64 * KROWB)               /* 9216 */
#define NBUF  4
#define QROWS 128
#define SM_K0  0
#define SM_V0  (NBUF * KTILEB)            /* 36864 */
#define ATT_SMEM (2 * NBUF * KTILEB)      /* 73728: 3 CTAs/SM */
#define NT (SEQ / 64)

__global__ void __launch_bounds__(256, 3)
flash_hmma()
{
    extern __shared__ __align__(128) char smem[];
    const uint32_t sb = smem_u32(smem);
    const int tid = threadIdx.x, ln = tid & 31, w = tid >> 5;
    const int qt = blockIdx.x, bh = blockIdx.y;

    const __half* qg = g_qh + ((size_t)bh * SEQ + qt * QROWS) * 64;
    const __half* kg = g_kh + (size_t)bh * SEQ * 64;
    const __half* vg = g_vh + (size_t)bh * SEQ * 64;

#define ATT_LOAD(t) do {                                                       \
        int buf_ = (t) & 3;                                                    \
        const __half* kb_ = kg + (size_t)(t) * 64 * 64;                        \
        const __half* vb_ = vg + (size_t)(t) * 64 * 64;                        \
        uint32_t kd_ = sb + SM_K0 + buf_ * KTILEB;                             \
        uint32_t vd_ = sb + SM_V0 + buf_ * KTILEB;                             \
        _Pragma("unroll")                                                      \
        for (int u_ = 0; u_ < 2; u_++) {                                       \
            int e_ = tid + u_ * 256;                                           \
            int row_ = e_ >> 3, seg_ = (e_ & 7) * 16;                          \
            cpa16(kd_ + row_ * KROWB + seg_,                                   \
                  (const char*)(kb_ + (size_t)row_ * 64) + seg_);              \
            cpa16(vd_ + row_ * KROWB + seg_,                                   \
                  (const char*)(vb_ + (size_t)row_ * 64) + seg_);              \
        }                                                                      \
        CP_COMMIT();                                                           \
    } while (0)

    ATT_LOAD(0); ATT_LOAD(1); ATT_LOAD(2);

    // Q fragments straight from gmem (A m16k16 fragment layout)
    uint32_t qf[4][4];
    {
        const __half* q0 = qg + (size_t)(w * 16 + (ln >> 2)) * 64 + (ln & 3) * 2;
        const __half* q8 = q0 + 8 * 64;
#pragma unroll
        for (int s = 0; s < 4; s++) {
            qf[s][0] = *(const uint32_t*)(q0 + s * 16);
            qf[s][1] = *(const uint32_t*)(q8 + s * 16);
            qf[s][2] = *(const uint32_t*)(q0 + s * 16 + 8);
            qf[s][3] = *(const uint32_t*)(q8 + s * 16 + 8);
        }
    }

    const int krow8  = (ln & 7) + ((ln & 16) ? 8 : 0);
    const int kcol8  = (ln & 8) ? 8 : 0;
    const int vrow16 = ln & 15;
    const int vcol8  = (ln & 16) ? 8 : 0;

    float m0 = -1e30f, m1 = -1e30f;
    float lp0 = 0.f, lp1 = 0.f;
    float acco[8][4] = {};

#pragma unroll 1
    for (int i = 0; i < NT; i++) {
        {
            const int rem = NT - 1 - i;
            if      (rem >= 2) CP_WAIT(2);
            else if (rem == 1) CP_WAIT(1);
            else               CP_WAIT(0);
        }
        __syncthreads();
        if (i + 3 < NT) ATT_LOAD(i + 3);

        const uint32_t bK = sb + SM_K0 + (i & 3) * KTILEB;
        const uint32_t bV = sb + SM_V0 + (i & 3) * KTILEB;

        // ---- S = Q K^T, fp16 accumulators, kept PACKED ----
        uint32_t sh[8][2] = {};
#pragma unroll
        for (int ks = 0; ks < 4; ks++) {
#pragma unroll
            for (int nbp = 0; nbp < 4; nbp++) {
                uint32_t kb[4];
                ldsm_x4(kb, bK + (nbp * 16 + krow8) * KROWB + (ks * 16 + kcol8) * 2);
                mma16816hh(sh[2 * nbp],     qf[ks], kb[0], kb[1]);
                mma16816hh(sh[2 * nbp + 1], qf[ks], kb[2], kb[3]);
            }
        }

        // ---- row max on packed halves (exact: S already fp16) ----
        uint32_t u0 = sh[0][0], u1 = sh[0][1];
#pragma unroll
        for (int jj = 1; jj < 8; jj++) {
            u0 = hmax2(u0, sh[jj][0]);
            u1 = hmax2(u1, sh[jj][1]);
        }
        u0 = hmax2(u0, __shfl_xor_sync(0xffffffffu, u0, 1));
        u0 = hmax2(u0, __shfl_xor_sync(0xffffffffu, u0, 2));
        u1 = hmax2(u1, __shfl_xor_sync(0xffffffffu, u1, 1));
        u1 = hmax2(u1, __shfl_xor_sync(0xffffffffu, u1, 2));
        float mx0, mx1;
        {
            __half2 p0 = reinterpret_cast<__half2&>(u0);
            __half2 p1 = reinterpret_cast<__half2&>(u1);
            mx0 = fmaxf(__low2float(p0), __high2float(p0));
            mx1 = fmaxf(__low2float(p1), __high2float(p1));
        }
        const float mn0 = fmaxf(m0, mx0), mn1 = fmaxf(m1, mx1);
        const float a0 = ex2(m0 - mn0), a1 = ex2(m1 - mn1);
        m0 = mn0; m1 = mn1;
        lp0 *= a0; lp1 *= a1;
#pragma unroll
        for (int jj = 0; jj < 8; jj++) {
            acco[jj][0] *= a0; acco[jj][1] *= a0;
            acco[jj][2] *= a1; acco[jj][3] *= a1;
        }

        // ---- unpack-on-the-fly exp -> pack -> PV ----
#pragma unroll
        for (int ks = 0; ks < 4; ks++) {
            __half2 A0 = reinterpret_cast<__half2&>(sh[2 * ks][0]);      // row r
            __half2 A1 = reinterpret_cast<__half2&>(sh[2 * ks][1]);      // row r+8
            __half2 B0 = reinterpret_cast<__half2&>(sh[2 * ks + 1][0]);
            __half2 B1 = reinterpret_cast<__half2&>(sh[2 * ks + 1][1]);
            float e00 = ex2(__low2float(A0) - m0);
            float e01 = ex2(__high2float(A0) - m0);
            float e02 = ex2(__low2float(A1) - m1);
            float e03 = ex2(__high2float(A1) - m1);
            float e10 = ex2(__low2float(B0) - m0);
            float e11 = ex2(__high2float(B0) - m0);
            float e12 = ex2(__low2float(B1) - m1);
            float e13 = ex2(__high2float(B1) - m1);
            lp0 += e00 + e01 + e10 + e11;
            lp1 += e02 + e03 + e12 + e13;
            uint32_t phi[4];
            phi[0] = packh2(e00, e01);
            phi[1] = packh2(e02, e03);
            phi[2] = packh2(e10, e11);
            phi[3] = packh2(e12, e13);
#pragma unroll
            for (int nbp = 0; nbp < 4; nbp++) {
                uint32_t vb[4];
                ldsm_x4t(vb, bV + (ks * 16 + vrow16) * KROWB + (nbp * 16 + vcol8) * 2);
                mma16816h(acco[2 * nbp],     phi, vb[0], vb[1]);
                mma16816h(acco[2 * nbp + 1], phi, vb[2], vb[3]);
            }
        }
    }

    // ---- epilogue: quad-reduce l once, normalize, write fp16 ----
    float l0 = lp0, l1 = lp1;
    l0 += __shfl_xor_sync(0xffffffffu, l0, 1);
    l0 += __shfl_xor_sync(0xffffffffu, l0, 2);
    l1 += __shfl_xor_sync(0xffffffffu, l1, 1);
    l1 += __shfl_xor_sync(0xffffffffu, l1, 2);

    const int b = bh >> 4, h = bh & 15;
    const int q = ln >> 2, t4 = ln & 3;
    const float inv0 = 1.f / l0, inv1 = 1.f / l1;
    const size_t n0 = (size_t)qt * QROWS + w * 16 + q;
    const size_t mg0 = (size_t)b * SEQ + n0;
    const size_t mg1 = mg0 + 8;
#pragma unroll
    for (int jj = 0; jj < 8; jj++) {
        const int col = h * 64 + jj * 8 + t4 * 2;
        *(uint32_t*)(g_ao + mg0 * D_MODEL + col) =
            packh2(acco[jj][0] * inv0, acco[jj][1] * inv0);
        *(uint32_t*)(g_ao + mg1 * D_MODEL + col) =
            packh2(acco[jj][2] * inv1, acco[jj][3] * inv1);
    }
}

// ---------------- launch --------------------------------------------------
extern "C" void kernel_launch(void* const* d_in, const int* in_sizes, int n_in,
                              void* d_out, int out_size)
{
    const float* x = (const float*)d_in[0];
    const float* W [4] = {(const float*)d_in[1],  (const float*)d_in[5],
                          (const float*)d_in[9],  (const float*)d_in[13]};
    const float* B [4] = {(const float*)d_in[2],  (const float*)d_in[6],
                          (const float*)d_in[10], (const float*)d_in[14]};
    const float* dW[4] = {(const float*)d_in[3],  (const float*)d_in[7],
                          (const float*)d_in[11], (const float*)d_in[15]};
    const float* dB[4] = {(const float*)d_in[4],  (const float*)d_in[8],
                          (const float*)d_in[12], (const float*)d_in[16]};
    float* out = (float*)d_out;

    void *pxh, *pao;
    cudaGetSymbolAddress(&pxh, g_xh);
    cudaGetSymbolAddress(&pao, g_ao);

    // 1) tiled LoRA merge + x->fp16
    {
        dim3 grid(4, 32, 4);
        merge_lora_t<<<grid, 256>>>(W[0], dW[0], dB[0], W[1], dW[1], dB[1],
                                    W[2], dW[2], dB[2], W[3], dW[3], dB[3]);
    }
    prep_h<<<4096, 256>>>(x);

    // 2) QKV projections
    cudaFuncSetAttribute(gemm_hmma, cudaFuncAttributeMaxDynamicSharedMemorySize, GSMEM);
    {
        dim3 grid(D_MODEL / 64, M_TOTAL / 128, 3);
        gemm_hmma<<<grid, 256, GSMEM>>>((const __half*)pxh, 0, 0,
                                        B[0], B[1], B[2], nullptr);
    }

    // 3) flash attention -> g_ao (3 CTAs/SM)
    cudaFuncSetAttribute(flash_hmma, cudaFuncAttributeMaxDynamicSharedMemorySize, ATT_SMEM);
    {
        dim3 grid(SEQ / QROWS, BATCH * NHEAD);
        flash_hmma<<<grid, 256, ATT_SMEM>>>();
    }

    // 4) O projection -> d_out
    {
        dim3 grid(D_MODEL / 64, M_TOTAL / 128, 1);
        gemm_hmma<<<grid, 256, GSMEM>>>((const __half*)pao, 1, 3,
                                        B[3], B[3], B[3], out);
    }
}

// round 17
// speedup vs baseline: 1.0314x; 1.0314x over previous
#include <cuda_runtime.h>
#include <cuda_fp16.h>
#include <cstdint>

#define D_MODEL 1024
#define NHEAD   16
#define DHEAD   64
#define SEQ     2048
#define BATCH   2
#define M_TOTAL (BATCH * SEQ)   /* 4096 */
#define RANK    32

// ---------------- device scratch (all single fp16) ----------------
__device__ __half g_xh [(size_t)M_TOTAL * D_MODEL];
__device__ __half g_w2 [(size_t)4 * D_MODEL * D_MODEL];
__device__ __half g_ao [(size_t)M_TOTAL * D_MODEL];
__device__ __half g_qh [(size_t)BATCH * NHEAD * SEQ * 64];  // Q * 0.125*log2e
__device__ __half g_kh [(size_t)BATCH * NHEAD * SEQ * 64];
__device__ __half g_vh [(size_t)BATCH * NHEAD * SEQ * 64];

// ---------------- PTX helpers (baseline PTX only) ----------------
__device__ __forceinline__ uint32_t smem_u32(const void* p) {
    uint32_t a;
    asm("{ .reg .u64 t; cvta.to.shared.u64 t, %1; cvt.u32.u64 %0, t; }" : "=r"(a) : "l"(p));
    return a;
}
__device__ __forceinline__ void cpa16(uint32_t dst, const void* src) {
    asm volatile("cp.async.cg.shared.global [%0], [%1], 16;" :: "r"(dst), "l"(src));
}
#define CP_COMMIT() asm volatile("cp.async.commit_group;" ::: "memory")
#define CP_WAIT(n)  asm volatile("cp.async.wait_group %0;" :: "n"(n) : "memory")

__device__ __forceinline__ void ldsm_x4(uint32_t (&r)[4], uint32_t addr) {
    asm volatile("ldmatrix.sync.aligned.m8n8.x4.shared.b16 {%0,%1,%2,%3}, [%4];"
                 : "=r"(r[0]), "=r"(r[1]), "=r"(r[2]), "=r"(r[3]) : "r"(addr));
}
__device__ __forceinline__ void ldsm_x4t(uint32_t (&r)[4], uint32_t addr) {
    asm volatile("ldmatrix.sync.aligned.m8n8.x4.trans.shared.b16 {%0,%1,%2,%3}, [%4];"
                 : "=r"(r[0]), "=r"(r[1]), "=r"(r[2]), "=r"(r[3]) : "r"(addr));
}
__device__ __forceinline__ void mma16816h(float (&d)[4], const uint32_t (&a)[4],
                                          uint32_t b0, uint32_t b1) {
    asm volatile("mma.sync.aligned.m16n8k16.row.col.f32.f16.f16.f32 "
                 "{%0,%1,%2,%3}, {%4,%5,%6,%7}, {%8,%9}, {%0,%1,%2,%3};"
                 : "+f"(d[0]), "+f"(d[1]), "+f"(d[2]), "+f"(d[3])
                 : "r"(a[0]), "r"(a[1]), "r"(a[2]), "r"(a[3]), "r"(b0), "r"(b1));
}
__device__ __forceinline__ void mma16816hh(uint32_t (&d)[2], const uint32_t (&a)[4],
                                           uint32_t b0, uint32_t b1) {
    asm volatile("mma.sync.aligned.m16n8k16.row.col.f16.f16.f16.f16 "
                 "{%0,%1}, {%2,%3,%4,%5}, {%6,%7}, {%0,%1};"
                 : "+r"(d[0]), "+r"(d[1])
                 : "r"(a[0]), "r"(a[1]), "r"(a[2]), "r"(a[3]), "r"(b0), "r"(b1));
}
__device__ __forceinline__ uint32_t packh2(float v0, float v1) {
    __half2 t = __floats2half2_rn(v0, v1);
    return reinterpret_cast<uint32_t&>(t);
}
__device__ __forceinline__ float ex2(float x) {
    float y;
    asm("ex2.approx.ftz.f32 %0, %1;" : "=f"(y) : "f"(x));
    return y;
}
__device__ __forceinline__ uint32_t hmax2(uint32_t a, uint32_t b) {
    uint32_t d;
    asm("max.f16x2 %0, %1, %2;" : "=r"(d) : "r"(a), "r"(b));
    return d;
}

// ---------------- smem-tiled LoRA merge (unchanged, known-good) ------------
__global__ void __launch_bounds__(256)
merge_lora_t(const float* __restrict__ W0, const float* __restrict__ dW0, const float* __restrict__ dB0,
             const float* __restrict__ W1, const float* __restrict__ dW1, const float* __restrict__ dB1,
             const float* __restrict__ W2, const float* __restrict__ dW2, const float* __restrict__ dB2,
             const float* __restrict__ W3, const float* __restrict__ dW3, const float* __restrict__ dB3)
{
    const int kx = blockIdx.x;
    const int ny = blockIdx.y;
    const int layer = blockIdx.z;
    const float* W  = (layer == 0) ? W0  : (layer == 1) ? W1  : (layer == 2) ? W2  : W3;
    const float* dW = (layer == 0) ? dW0 : (layer == 1) ? dW1 : (layer == 2) ? dW2 : dW3;
    const float* dB = (layer == 0) ? dB0 : (layer == 1) ? dB1 : (layer == 2) ? dB2 : dB3;

    __shared__ float4 dws[RANK][64];
    __shared__ float  dbs[32][RANK];

    const int tid = threadIdx.x;
    const float4* dW4 = (const float4*)dW;
    const int n0 = ny * 32;

#pragma unroll
    for (int i = 0; i < 8; i++) {
        int e = tid + i * 256;
        int r = e >> 6, q = e & 63;
        dws[r][q] = dW4[r * 256 + kx * 64 + q];
    }
#pragma unroll
    for (int i = 0; i < 4; i++) {
        int e = tid + i * 256;
        int row = e >> 5, r = e & 31;
        dbs[row][r] = dB[(n0 + row) * RANK + r];
    }
    __syncthreads();

    const int q    = tid & 63;
    const int rowg = tid >> 6;
    const float4* W4 = (const float4*)W;
    float4 s[8];
#pragma unroll
    for (int j = 0; j < 8; j++)
        s[j] = W4[(size_t)(n0 + rowg * 8 + j) * 256 + kx * 64 + q];
#pragma unroll
    for (int r = 0; r < RANK; r++) {
        float4 w = dws[r][q];
#pragma unroll
        for (int j = 0; j < 8; j++) {
            float b = dbs[rowg * 8 + j][r];
            s[j].x += b * w.x; s[j].y += b * w.y;
            s[j].z += b * w.z; s[j].w += b * w.w;
        }
    }
#pragma unroll
    for (int j = 0; j < 8; j++) {
        int n = n0 + rowg * 8 + j;
        __half2* p = (__half2*)(g_w2 + (size_t)(layer * D_MODEL + n) * D_MODEL
                                + (kx * 64 + q) * 4);
        p[0] = __floats2half2_rn(s[j].x, s[j].y);
        p[1] = __floats2half2_rn(s[j].z, s[j].w);
    }
}

// ---------------- x -> single fp16 ----------------
__global__ void prep_h(const float* __restrict__ src)
{
    int e = blockIdx.x * 256 + threadIdx.x;
    float4 s = *(const float4*)(src + (size_t)e * 4);
    __half2* p = (__half2*)(g_xh + (size_t)e * 4);
    p[0] = __floats2half2_rn(s.x, s.y);
    p[1] = __floats2half2_rn(s.z, s.w);
}

// ---------------- HMMA GEMM (unchanged from round 15) ----------------------
#define GKC   64
#define GNCH  16
#define GROWB 144
#define GA_BYTES (128 * GROWB)
#define GW_BYTES (64 * GROWB)
#define GSTAGE   (GA_BYTES + GW_BYTES)
#define GSMEM    (2 * GSTAGE)

__global__ void __launch_bounds__(256, 3)
gemm_hmma(const __half* __restrict__ Abase,
          int mode, int layer_base,
          const float* __restrict__ b0, const float* __restrict__ b1,
          const float* __restrict__ b2, float* __restrict__ outO)
{
    extern __shared__ __align__(128) char smem[];
    const uint32_t sb = smem_u32(smem);
    const int tid = threadIdx.x, ln = tid & 31, w = tid >> 5;
    const int wm = w & 3, wn = w >> 2;
    const int bx = blockIdx.x, by = blockIdx.y, z = blockIdx.z;
    const int layer = layer_base + z;

    const __half* Arow = Abase + (size_t)(by * 128) * D_MODEL;
    const __half* Wrow = g_w2 + ((size_t)layer * D_MODEL + bx * 64) * D_MODEL;

    float acc[2][4][4] = {};

#define GLOAD(c) do {                                                          \
        int s_ = (c) & 1;                                                      \
        int x_ = (c) * GKC;                                                    \
        uint32_t bA_ = sb + s_ * GSTAGE;                                       \
        uint32_t bW_ = bA_ + GA_BYTES;                                         \
        _Pragma("unroll")                                                      \
        for (int u_ = 0; u_ < 4; u_++) {                                       \
            int e_ = tid + u_ * 256;                                           \
            int row_ = e_ >> 3, seg_ = (e_ & 7) * 16;                          \
            cpa16(bA_ + row_ * GROWB + seg_,                                   \
                  (const char*)(Arow + (size_t)row_ * D_MODEL + x_) + seg_);   \
        }                                                                      \
        _Pragma("unroll")                                                      \
        for (int u_ = 0; u_ < 2; u_++) {                                       \
            int e_ = tid + u_ * 256;                                           \
            int row_ = e_ >> 3, seg_ = (e_ & 7) * 16;                          \
            cpa16(bW_ + row_ * GROWB + seg_,                                   \
                  (const char*)(Wrow + (size_t)row_ * D_MODEL + x_) + seg_);   \
        }                                                                      \
        CP_COMMIT();                                                           \
    } while (0)

    GLOAD(0);
    for (int c = 0; c < GNCH; c++) {
        CP_WAIT(0);
        __syncthreads();
        if (c + 1 < GNCH) GLOAD(c + 1);

        const uint32_t bA = sb + (c & 1) * GSTAGE;
        const uint32_t bW = bA + GA_BYTES;
#pragma unroll
        for (int ks = 0; ks < 4; ks++) {
            const int k0 = ks * 16;
            uint32_t afr[2][4];
#pragma unroll
            for (int i = 0; i < 2; i++) {
                int row = wm * 32 + i * 16 + (ln & 15);
                ldsm_x4(afr[i], bA + row * GROWB + (k0 + ((ln >> 4) << 3)) * 2);
            }
            uint32_t bfr[2][4];
#pragma unroll
            for (int j = 0; j < 2; j++) {
                int n = wn * 32 + j * 16 + (ln & 7) + ((ln & 16) ? 8 : 0);
                ldsm_x4(bfr[j], bW + n * GROWB + (k0 + ((ln & 8) ? 8 : 0)) * 2);
            }
#pragma unroll
            for (int i = 0; i < 2; i++)
#pragma unroll
                for (int jj = 0; jj < 4; jj++)
                    mma16816h(acc[i][jj], afr[i], bfr[jj >> 1][(jj & 1) * 2],
                              bfr[jj >> 1][(jj & 1) * 2 + 1]);
        }
    }

    const float* bias = (z == 0) ? b0 : (z == 1) ? b1 : b2;
    const float qscale = (mode == 0 && z == 0) ? 0.125f * 1.4426950408889634f : 1.0f;
#pragma unroll
    for (int i = 0; i < 2; i++) {
#pragma unroll
        for (int dl = 0; dl < 2; dl++) {
            const int m = by * 128 + wm * 32 + i * 16 + (ln >> 2) + dl * 8;
#pragma unroll
            for (int jj = 0; jj < 4; jj++) {
                const int cgl = bx * 64 + wn * 32 + jj * 8 + (ln & 3) * 2;
                float v0 = (acc[i][jj][dl * 2 + 0] + bias[cgl])     * qscale;
                float v1 = (acc[i][jj][dl * 2 + 1] + bias[cgl + 1]) * qscale;
                if (mode == 0) {
                    const int h = cgl >> 6, d = cgl & 63;
                    const int b = m >> 11, n = m & 2047;
                    const size_t rowb = (size_t)(b * NHEAD + h) * SEQ + n;
                    __half* base = ((z == 0) ? g_qh : (z == 1) ? g_kh : g_vh)
                                   + rowb * 64 + d;
                    *(__half2*)base = __floats2half2_rn(v0, v1);
                } else {
                    float2 o; o.x = v0; o.y = v1;
                    *(float2*)(outO + (size_t)m * D_MODEL + cgl) = o;
                }
            }
        }
    }
}

// ---------------- Flash attention: packed-fp16 S, 2 CTAs/SM, NBUF=6 --------
#define KROWB 144
#define KTILEB (64 * KROWB)               /* 9216 */
#define NBUF  6
#define QROWS 128
#define SM_K0  0
#define SM_V0  (NBUF * KTILEB)            /* 55296 */
#define ATT_SMEM (2 * NBUF * KTILEB)      /* 110592: 2 CTAs/SM */
#define NT (SEQ / 64)

__global__ void __launch_bounds__(256, 2)
flash_hmma()
{
    extern __shared__ __align__(128) char smem[];
    const uint32_t sb = smem_u32(smem);
    const int tid = threadIdx.x, ln = tid & 31, w = tid >> 5;
    const int qt = blockIdx.x, bh = blockIdx.y;

    const __half* qg = g_qh + ((size_t)bh * SEQ + qt * QROWS) * 64;
    const __half* kg = g_kh + (size_t)bh * SEQ * 64;
    const __half* vg = g_vh + (size_t)bh * SEQ * 64;

#define ATT_LOAD(t) do {                                                       \
        int buf_ = (t) % NBUF;                                                 \
        const __half* kb_ = kg + (size_t)(t) * 64 * 64;                        \
        const __half* vb_ = vg + (size_t)(t) * 64 * 64;                        \
        uint32_t kd_ = sb + SM_K0 + buf_ * KTILEB;                             \
        uint32_t vd_ = sb + SM_V0 + buf_ * KTILEB;                             \
        _Pragma("unroll")                                                      \
        for (int u_ = 0; u_ < 2; u_++) {                                       \
            int e_ = tid + u_ * 256;                                           \
            int row_ = e_ >> 3, seg_ = (e_ & 7) * 16;                          \
            cpa16(kd_ + row_ * KROWB + seg_,                                   \
                  (const char*)(kb_ + (size_t)row_ * 64) + seg_);              \
            cpa16(vd_ + row_ * KROWB + seg_,                                   \
                  (const char*)(vb_ + (size_t)row_ * 64) + seg_);              \
        }                                                                      \
        CP_COMMIT();                                                           \
    } while (0)

    ATT_LOAD(0); ATT_LOAD(1); ATT_LOAD(2); ATT_LOAD(3); ATT_LOAD(4);

    // Q fragments straight from gmem (A m16k16 fragment layout)
    uint32_t qf[4][4];
    {
        const __half* q0 = qg + (size_t)(w * 16 + (ln >> 2)) * 64 + (ln & 3) * 2;
        const __half* q8 = q0 + 8 * 64;
#pragma unroll
        for (int s = 0; s < 4; s++) {
            qf[s][0] = *(const uint32_t*)(q0 + s * 16);
            qf[s][1] = *(const uint32_t*)(q8 + s * 16);
            qf[s][2] = *(const uint32_t*)(q0 + s * 16 + 8);
            qf[s][3] = *(const uint32_t*)(q8 + s * 16 + 8);
        }
    }

    const int krow8  = (ln & 7) + ((ln & 16) ? 8 : 0);
    const int kcol8  = (ln & 8) ? 8 : 0;
    const int vrow16 = ln & 15;
    const int vcol8  = (ln & 16) ? 8 : 0;

    float m0 = -1e30f, m1 = -1e30f;
    float lp0 = 0.f, lp1 = 0.f;
    float acco[8][4] = {};

#pragma unroll 1
    for (int i = 0; i < NT; i++) {
        {
            const int rem = NT - 1 - i;
            if      (rem >= 4) CP_WAIT(4);
            else if (rem == 3) CP_WAIT(3);
            else if (rem == 2) CP_WAIT(2);
            else if (rem == 1) CP_WAIT(1);
            else               CP_WAIT(0);
        }
        __syncthreads();
        if (i + 5 < NT) ATT_LOAD(i + 5);

        const uint32_t bK = sb + SM_K0 + (i % NBUF) * KTILEB;
        const uint32_t bV = sb + SM_V0 + (i % NBUF) * KTILEB;

        // ---- S = Q K^T, fp16 accumulators, kept PACKED ----
        uint32_t sh[8][2] = {};
#pragma unroll
        for (int ks = 0; ks < 4; ks++) {
#pragma unroll
            for (int nbp = 0; nbp < 4; nbp++) {
                uint32_t kb[4];
                ldsm_x4(kb, bK + (nbp * 16 + krow8) * KROWB + (ks * 16 + kcol8) * 2);
                mma16816hh(sh[2 * nbp],     qf[ks], kb[0], kb[1]);
                mma16816hh(sh[2 * nbp + 1], qf[ks], kb[2], kb[3]);
            }
        }

        // ---- row max on packed halves (exact: S already fp16) ----
        uint32_t u0 = sh[0][0], u1 = sh[0][1];
#pragma unroll
        for (int jj = 1; jj < 8; jj++) {
            u0 = hmax2(u0, sh[jj][0]);
            u1 = hmax2(u1, sh[jj][1]);
        }
        u0 = hmax2(u0, __shfl_xor_sync(0xffffffffu, u0, 1));
        u0 = hmax2(u0, __shfl_xor_sync(0xffffffffu, u0, 2));
        u1 = hmax2(u1, __shfl_xor_sync(0xffffffffu, u1, 1));
        u1 = hmax2(u1, __shfl_xor_sync(0xffffffffu, u1, 2));
        float mx0, mx1;
        {
            __half2 p0 = reinterpret_cast<__half2&>(u0);
            __half2 p1 = reinterpret_cast<__half2&>(u1);
            mx0 = fmaxf(__low2float(p0), __high2float(p0));
            mx1 = fmaxf(__low2float(p1), __high2float(p1));
        }
        const float mn0 = fmaxf(m0, mx0), mn1 = fmaxf(m1, mx1);
        const float a0 = ex2(m0 - mn0), a1 = ex2(m1 - mn1);
        m0 = mn0; m1 = mn1;
        lp0 *= a0; lp1 *= a1;
#pragma unroll
        for (int jj = 0; jj < 8; jj++) {
            acco[jj][0] *= a0; acco[jj][1] *= a0;
            acco[jj][2] *= a1; acco[jj][3] *= a1;
        }

        // ---- unpack-on-the-fly exp -> pack -> PV ----
#pragma unroll
        for (int ks = 0; ks < 4; ks++) {
            __half2 A0 = reinterpret_cast<__half2&>(sh[2 * ks][0]);
            __half2 A1 = reinterpret_cast<__half2&>(sh[2 * ks][1]);
            __half2 B0 = reinterpret_cast<__half2&>(sh[2 * ks + 1][0]);
            __half2 B1 = reinterpret_cast<__half2&>(sh[2 * ks + 1][1]);
            float e00 = ex2(__low2float(A0) - m0);
            float e01 = ex2(__high2float(A0) - m0);
            float e02 = ex2(__low2float(A1) - m1);
            float e03 = ex2(__high2float(A1) - m1);
            float e10 = ex2(__low2float(B0) - m0);
            float e11 = ex2(__high2float(B0) - m0);
            float e12 = ex2(__low2float(B1) - m1);
            float e13 = ex2(__high2float(B1) - m1);
            lp0 += e00 + e01 + e10 + e11;
            lp1 += e02 + e03 + e12 + e13;
            uint32_t phi[4];
            phi[0] = packh2(e00, e01);
            phi[1] = packh2(e02, e03);
            phi[2] = packh2(e10, e11);
            phi[3] = packh2(e12, e13);
#pragma unroll
            for (int nbp = 0; nbp < 4; nbp++) {
                uint32_t vb[4];
                ldsm_x4t(vb, bV + (ks * 16 + vrow16) * KROWB + (nbp * 16 + vcol8) * 2);
                mma16816h(acco[2 * nbp],     phi, vb[0], vb[1]);
                mma16816h(acco[2 * nbp + 1], phi, vb[2], vb[3]);
            }
        }
    }

    // ---- epilogue: quad-reduce l once, normalize, write fp16 ----
    float l0 = lp0, l1 = lp1;
    l0 += __shfl_xor_sync(0xffffffffu, l0, 1);
    l0 += __shfl_xor_sync(0xffffffffu, l0, 2);
    l1 += __shfl_xor_sync(0xffffffffu, l1, 1);
    l1 += __shfl_xor_sync(0xffffffffu, l1, 2);

    const int b = bh >> 4, h = bh & 15;
    const int q = ln >> 2, t4 = ln & 3;
    const float inv0 = 1.f / l0, inv1 = 1.f / l1;
    const size_t n0 = (size_t)qt * QROWS + w * 16 + q;
    const size_t mg0 = (size_t)b * SEQ + n0;
    const size_t mg1 = mg0 + 8;
#pragma unroll
    for (int jj = 0; jj < 8; jj++) {
        const int col = h * 64 + jj * 8 + t4 * 2;
        *(uint32_t*)(g_ao + mg0 * D_MODEL + col) =
            packh2(acco[jj][0] * inv0, acco[jj][1] * inv0);
        *(uint32_t*)(g_ao + mg1 * D_MODEL + col) =
            packh2(acco[jj][2] * inv1, acco[jj][3] * inv1);
    }
}

// ---------------- launch --------------------------------------------------
extern "C" void kernel_launch(void* const* d_in, const int* in_sizes, int n_in,
                              void* d_out, int out_size)
{
    const float* x = (const float*)d_in[0];
    const float* W [4] = {(const float*)d_in[1],  (const float*)d_in[5],
                          (const float*)d_in[9],  (const float*)d_in[13]};
    const float* B [4] = {(const float*)d_in[2],  (const float*)d_in[6],
                          (const float*)d_in[10], (const float*)d_in[14]};
    const float* dW[4] = {(const float*)d_in[3],  (const float*)d_in[7],
                          (const float*)d_in[11], (const float*)d_in[15]};
    const float* dB[4] = {(const float*)d_in[4],  (const float*)d_in[8],
                          (const float*)d_in[12], (const float*)d_in[16]};
    float* out = (float*)d_out;

    void *pxh, *pao;
    cudaGetSymbolAddress(&pxh, g_xh);
    cudaGetSymbolAddress(&pao, g_ao);

    // 1) tiled LoRA merge + x->fp16
    {
        dim3 grid(4, 32, 4);
        merge_lora_t<<<grid, 256>>>(W[0], dW[0], dB[0], W[1], dW[1], dB[1],
                                    W[2], dW[2], dB[2], W[3], dW[3], dB[3]);
    }
    prep_h<<<4096, 256>>>(x);

    // 2) QKV projections
    cudaFuncSetAttribute(gemm_hmma, cudaFuncAttributeMaxDynamicSharedMemorySize, GSMEM);
    {
        dim3 grid(D_MODEL / 64, M_TOTAL / 128, 3);
        gemm_hmma<<<grid, 256, GSMEM>>>((const __half*)pxh, 0, 0,
                                        B[0], B[1], B[2], nullptr);
    }

    // 3) flash attention -> g_ao (packed S, 2 CTAs/SM, deep ring)
    cudaFuncSetAttribute(flash_hmma, cudaFuncAttributeMaxDynamicSharedMemorySize, ATT_SMEM);
    {
        dim3 grid(SEQ / QROWS, BATCH * NHEAD);
        flash_hmma<<<grid, 256, ATT_SMEM>>>();
    }

    // 4) O projection -> d_out
    {
        dim3 grid(D_MODEL / 64, M_TOTAL / 128, 1);
        gemm_hmma<<<grid, 256, GSMEM>>>((const __half*)pao, 1, 3,
                                        B[3], B[3], B[3], out);
    }
}